// round 2
// baseline (speedup 1.0000x reference)
#include <cuda_runtime.h>

// LengthRegulator: b=16, t_x=1024, d=256, out_len = 1024*(8-1) = 7168
// out[b, j, :] = x[b, phoneme(j), :]  (gather), lengths[b] = sum(rep[b,:])
// NOTE: repeat_count is int32 (JAX x64 disabled downgrades jnp.int64 -> int32).

#define B_DIM   16
#define TX      1024
#define D_DIM   256
#define OUT_LEN 7168          // t_x * (max_dur - 1)
#define D_VEC   (D_DIM / 4)   // 64 float4 per row

// scratch: frame -> phoneme index (-1 = past end, write zeros)
__device__ int g_map[B_DIM * OUT_LEN];

// ---------------------------------------------------------------------------
// Kernel 1: per-batch inclusive scan of repeat_count, build frame->phoneme map,
// emit lengths (as float) into the tail of d_out.
// grid = B_DIM blocks, block = TX threads.
// ---------------------------------------------------------------------------
__global__ void scan_and_map_kernel(const int* __restrict__ rep,
                                    float* __restrict__ out,
                                    int out_size) {
    __shared__ int s[TX];
    const int b = blockIdx.x;
    const int t = threadIdx.x;

    const int v = rep[b * TX + t];
    s[t] = v;
    __syncthreads();

    // Hillis-Steele inclusive scan
    #pragma unroll
    for (int off = 1; off < TX; off <<= 1) {
        int add = (t >= off) ? s[t - off] : 0;
        __syncthreads();
        s[t] += add;
        __syncthreads();
    }
    const int cum = s[t];          // inclusive prefix sum for phoneme t
    const int start = cum - v;

    // init map to -1
    int* map_b = g_map + b * OUT_LEN;
    for (int j = t; j < OUT_LEN; j += TX) map_b[j] = -1;
    __syncthreads();

    // scatter this phoneme's span (at most max_dur-1 = 7 entries)
    for (int j = start; j < cum; ++j) map_b[j] = t;

    // lengths[b] = total = cum of last phoneme (cumsum of nonneg -> max == last)
    if (t == TX - 1) {
        const size_t main_elems = (size_t)B_DIM * OUT_LEN * D_DIM;
        if ((size_t)out_size > main_elems)
            out[main_elems + b] = (float)cum;
    }
}

// ---------------------------------------------------------------------------
// Kernel 2: expand. Each 64-thread group copies one output frame (256 floats)
// as 64 float4's. grid = (OUT_LEN/4, B_DIM), block = 256.
// ---------------------------------------------------------------------------
__global__ void expand_kernel(const float4* __restrict__ x4,
                              float4* __restrict__ out4) {
    const int b     = blockIdx.y;
    const int frame = blockIdx.x * 4 + (threadIdx.x >> 6);
    const int lane  = threadIdx.x & 63;

    const int ph = g_map[b * OUT_LEN + frame];

    float4 v = make_float4(0.f, 0.f, 0.f, 0.f);
    if (ph >= 0)
        v = x4[((size_t)b * TX + ph) * D_VEC + lane];

    out4[((size_t)b * OUT_LEN + frame) * D_VEC + lane] = v;
}

// ---------------------------------------------------------------------------
extern "C" void kernel_launch(void* const* d_in, const int* in_sizes, int n_in,
                              void* d_out, int out_size) {
    const float* x   = (const float*)d_in[0];   // (16,1024,256) fp32
    const int*   rep = (const int*)d_in[1];     // (16,1024) int32 (see note)
    float* out = (float*)d_out;

    scan_and_map_kernel<<<B_DIM, TX>>>(rep, out, out_size);

    dim3 grid(OUT_LEN / 4, B_DIM);
    expand_kernel<<<grid, 256>>>((const float4*)x, (float4*)out);
}

// round 3
// speedup vs baseline: 1.1670x; 1.1670x over previous
#include <cuda_runtime.h>

// LengthRegulator: b=16, t_x=1024, d=256, out_len = 1024*(8-1) = 7168
// out[b, j, :] = x[b, phoneme(j), :]  (gather), lengths[b] = sum(rep[b,:])

#define B_DIM   16
#define TX      1024
#define D_DIM   256
#define OUT_LEN 7168          // t_x * (max_dur - 1)
#define D_VEC   (D_DIM / 4)   // 64 float4 per row
#define FPT     8             // frames per 64-thread group in expand

// scratch: frame -> phoneme index (-1 = past end, write zeros)
__device__ int g_map[B_DIM * OUT_LEN];

// ---------------------------------------------------------------------------
// Kernel 1: per-batch inclusive scan (warp-shuffle), build frame->phoneme map,
// emit lengths (as float) into the tail of d_out.
// grid = B_DIM blocks, block = TX threads (32 warps).
// ---------------------------------------------------------------------------
__global__ void scan_and_map_kernel(const int* __restrict__ rep,
                                    float* __restrict__ out,
                                    int out_size) {
    __shared__ int warp_tot[32];
    __shared__ int s_total;

    const int b    = blockIdx.x;
    const int t    = threadIdx.x;
    const int lane = t & 31;
    const int wid  = t >> 5;

    const int v = rep[b * TX + t];

    // warp-level inclusive scan
    int sum = v;
    #pragma unroll
    for (int off = 1; off < 32; off <<= 1) {
        int n = __shfl_up_sync(0xFFFFFFFFu, sum, off);
        if (lane >= off) sum += n;
    }
    if (lane == 31) warp_tot[wid] = sum;
    __syncthreads();

    // scan the 32 warp totals in warp 0
    if (wid == 0) {
        int w = warp_tot[lane];
        #pragma unroll
        for (int off = 1; off < 32; off <<= 1) {
            int n = __shfl_up_sync(0xFFFFFFFFu, w, off);
            if (lane >= off) w += n;
        }
        warp_tot[lane] = w;                       // inclusive warp-prefix
        if (lane == 31) s_total = w;              // grand total
    }
    __syncthreads();

    const int cum   = sum + (wid > 0 ? warp_tot[wid - 1] : 0); // inclusive
    const int start = cum - v;
    const int total = s_total;

    int* map_b = g_map + b * OUT_LEN;

    // init only the tail (frames past total length) to -1
    for (int j = total + t; j < OUT_LEN; j += TX) map_b[j] = -1;

    // scatter this phoneme's span (at most max_dur-1 = 7 entries); disjoint
    // from the tail region, so no sync needed.
    for (int j = start; j < cum; ++j) map_b[j] = t;

    // lengths[b] = total (cumsum of nonneg -> max == last)
    if (t == 0) {
        const size_t main_elems = (size_t)B_DIM * OUT_LEN * D_DIM;
        if ((size_t)out_size > main_elems)
            out[main_elems + b] = (float)total;
    }
}

// ---------------------------------------------------------------------------
// Kernel 2: expand. Each 64-thread group copies FPT frames (independent
// gather chains -> high MLP). grid = (OUT_LEN/(4*FPT), B_DIM), block = 256.
// ---------------------------------------------------------------------------
__global__ void __launch_bounds__(256)
expand_kernel(const float4* __restrict__ x4, float4* __restrict__ out4) {
    const int b     = blockIdx.y;
    const int group = blockIdx.x * 4 + (threadIdx.x >> 6);
    const int lane  = threadIdx.x & 63;
    const int base  = group * FPT;               // first frame for this group

    // batch the (broadcast) map loads
    int ph[FPT];
    #pragma unroll
    for (int k = 0; k < FPT; ++k)
        ph[k] = g_map[b * OUT_LEN + base + k];

    // independent gathers -> MLP = FPT
    float4 v[FPT];
    #pragma unroll
    for (int k = 0; k < FPT; ++k) {
        v[k] = make_float4(0.f, 0.f, 0.f, 0.f);
        if (ph[k] >= 0)
            v[k] = x4[((size_t)b * TX + ph[k]) * D_VEC + lane];
    }

    // coalesced stores: each frame = 1KB contiguous, frames consecutive
    #pragma unroll
    for (int k = 0; k < FPT; ++k)
        out4[((size_t)b * OUT_LEN + base + k) * D_VEC + lane] = v[k];
}

// ---------------------------------------------------------------------------
extern "C" void kernel_launch(void* const* d_in, const int* in_sizes, int n_in,
                              void* d_out, int out_size) {
    const float* x   = (const float*)d_in[0];   // (16,1024,256) fp32
    const int*   rep = (const int*)d_in[1];     // (16,1024) int32
    float* out = (float*)d_out;

    scan_and_map_kernel<<<B_DIM, TX>>>(rep, out, out_size);

    dim3 grid(OUT_LEN / (4 * FPT), B_DIM);      // (224, 16)
    expand_kernel<<<grid, 256>>>((const float4*)x, (float4*)out);
}

// round 5
// speedup vs baseline: 1.2209x; 1.0462x over previous
#include <cuda_runtime.h>

// LengthRegulator: b=16, t_x=1024, d=256, out_len = 1024*(8-1) = 7168
// out[b, j, :] = x[b, phoneme(j), :]  (gather), lengths[b] = sum(rep[b,:])

#define B_DIM   16
#define TX      1024
#define D_DIM   256
#define OUT_LEN 7168          // t_x * (max_dur - 1)
#define D_VEC   (D_DIM / 4)   // 64 float4 per row
#define FPT     8             // frames per 64-thread group in expand
#define FRAMES_PER_BLK 32     // 4 groups * FPT

// per-batch inclusive cumsum of repeat_count
__device__ int g_cum[B_DIM * TX];

// ---------------------------------------------------------------------------
// Kernel 1: per-batch inclusive scan (warp-shuffle). Writes cumsum (coalesced)
// and lengths (as float) into the tail of d_out. grid=16, block=1024.
// ---------------------------------------------------------------------------
__global__ void scan_kernel(const int* __restrict__ rep,
                            float* __restrict__ out,
                            int out_size) {
    __shared__ int warp_tot[32];

    const int b    = blockIdx.x;
    const int t    = threadIdx.x;
    const int lane = t & 31;
    const int wid  = t >> 5;

    const int v = rep[b * TX + t];

    int sum = v;
    #pragma unroll
    for (int off = 1; off < 32; off <<= 1) {
        int n = __shfl_up_sync(0xFFFFFFFFu, sum, off);
        if (lane >= off) sum += n;
    }
    if (lane == 31) warp_tot[wid] = sum;
    __syncthreads();

    if (wid == 0) {
        int w = warp_tot[lane];
        #pragma unroll
        for (int off = 1; off < 32; off <<= 1) {
            int n = __shfl_up_sync(0xFFFFFFFFu, w, off);
            if (lane >= off) w += n;
        }
        warp_tot[lane] = w;   // inclusive prefix of warp totals
    }
    __syncthreads();

    const int cum = sum + (wid > 0 ? warp_tot[wid - 1] : 0);
    g_cum[b * TX + t] = cum;

    // lengths[b] = grand total (nonneg reps -> max(cumsum) == last)
    if (t == TX - 1) {
        const size_t main_elems = (size_t)B_DIM * OUT_LEN * D_DIM;
        if ((size_t)out_size > main_elems)
            out[main_elems + b] = (float)cum;
    }
}

// ---------------------------------------------------------------------------
// Kernel 2: expand. Block = 256 threads handles 32 consecutive frames of one
// batch. Loads the batch cumsum into smem, 32 threads binary-search the
// phoneme for each frame, then 4 groups of 64 lanes gather+store FPT frames
// each as float4 (coalesced 1KB rows, MLP = FPT).
// grid = (OUT_LEN/32, B_DIM) = (224, 16)
// ---------------------------------------------------------------------------
__global__ void __launch_bounds__(256)
expand_kernel(const float4* __restrict__ x4, float4* __restrict__ out4) {
    __shared__ int s_cum[TX];
    __shared__ int s_ph[FRAMES_PER_BLK];

    const int b    = blockIdx.y;
    const int base = blockIdx.x * FRAMES_PER_BLK;
    const int tid  = threadIdx.x;

    // load batch cumsum row (4KB) into smem, one int4 per thread
    ((int4*)s_cum)[tid] = ((const int4*)(g_cum + b * TX))[tid];
    __syncthreads();

    // 32 threads: one binary search per frame in this block's range
    if (tid < FRAMES_PER_BLK) {
        const int j = base + tid;
        const int total = s_cum[TX - 1];
        int ph = -1;
        if (j < total) {
            // lower_bound: first i with s_cum[i] > j. Invariant: answer in
            // [lo, hi]; width 1024 -> needs 11 iterations to reach lo==hi.
            // Extra iterations after convergence are no-ops (s_cum[lo] > j).
            int lo = 0, hi = TX;
            #pragma unroll
            for (int it = 0; it < 11; ++it) {
                int mid = (lo + hi) >> 1;
                if (s_cum[mid] > j) hi = mid; else lo = mid + 1;
            }
            ph = lo;
        }
        s_ph[tid] = ph;
    }
    __syncthreads();

    const int group = tid >> 6;          // 0..3
    const int lane  = tid & 63;
    const int f0    = group * FPT;       // group's first frame within block

    int ph[FPT];
    #pragma unroll
    for (int k = 0; k < FPT; ++k) ph[k] = s_ph[f0 + k];

    float4 v[FPT];
    #pragma unroll
    for (int k = 0; k < FPT; ++k) {
        v[k] = make_float4(0.f, 0.f, 0.f, 0.f);
        if (ph[k] >= 0)
            v[k] = x4[((size_t)b * TX + ph[k]) * D_VEC + lane];
    }

    #pragma unroll
    for (int k = 0; k < FPT; ++k)
        out4[((size_t)b * OUT_LEN + base + f0 + k) * D_VEC + lane] = v[k];
}

// ---------------------------------------------------------------------------
extern "C" void kernel_launch(void* const* d_in, const int* in_sizes, int n_in,
                              void* d_out, int out_size) {
    const float* x   = (const float*)d_in[0];   // (16,1024,256) fp32
    const int*   rep = (const int*)d_in[1];     // (16,1024) int32
    float* out = (float*)d_out;

    scan_kernel<<<B_DIM, TX>>>(rep, out, out_size);

    dim3 grid(OUT_LEN / FRAMES_PER_BLK, B_DIM); // (224, 16)
    expand_kernel<<<grid, 256>>>((const float4*)x, (float4*)out);
}

// round 6
// speedup vs baseline: 1.3117x; 1.0744x over previous
#include <cuda_runtime.h>

// LengthRegulator, fully fused single kernel.
// b=16, t_x=1024, d=256, out_len=7168.
// out[b, j, :] = x[b, phoneme(j), :]; lengths[b] = sum(rep[b,:]).

#define B_DIM   16
#define TX      1024
#define D_DIM   256
#define OUT_LEN 7168
#define D_VEC   (D_DIM / 4)      // 64 float4 per row
#define FPT     8                // frames per 64-lane group per batch
#define FRAMES_PER_BLK 64        // 4 groups * FPT * 2 batches
#define NWARP   8                // 256 threads

__global__ void __launch_bounds__(256)
fused_kernel(const float4* __restrict__ x4,
             const int*    __restrict__ rep,
             float*        __restrict__ out,
             int out_size) {
    __shared__ int s_cum[TX];
    __shared__ int s_ph[FRAMES_PER_BLK];
    __shared__ int warp_tot[NWARP];

    const int b    = blockIdx.y;
    const int base = blockIdx.x * FRAMES_PER_BLK;
    const int tid  = threadIdx.x;
    const int lane = tid & 31;
    const int wid  = tid >> 5;

    // ---- in-block scan of rep[b, :] (each thread owns 4 consecutive) ----
    const int4 r = ((const int4*)(rep + b * TX))[tid];
    const int p0 = r.x;
    const int p1 = p0 + r.y;
    const int p2 = p1 + r.z;
    const int p3 = p2 + r.w;                 // per-thread inclusive sums

    int ws = p3;                             // warp inclusive scan of p3
    #pragma unroll
    for (int off = 1; off < 32; off <<= 1) {
        int n = __shfl_up_sync(0xFFFFFFFFu, ws, off);
        if (lane >= off) ws += n;
    }
    if (lane == 31) warp_tot[wid] = ws;
    __syncthreads();

    if (wid == 0 && lane < NWARP) {          // scan the 8 warp totals
        int w = warp_tot[lane];
        #pragma unroll
        for (int off = 1; off < NWARP; off <<= 1) {
            int n = __shfl_up_sync(0xFFu, w, off);
            if (lane >= off) w += n;
        }
        warp_tot[lane] = w;                  // inclusive prefix
    }
    __syncthreads();

    const int off0 = (wid > 0 ? warp_tot[wid - 1] : 0) + (ws - p3);
    s_cum[4 * tid + 0] = off0 + p0;
    s_cum[4 * tid + 1] = off0 + p1;
    s_cum[4 * tid + 2] = off0 + p2;
    s_cum[4 * tid + 3] = off0 + p3;
    __syncthreads();

    const int total = s_cum[TX - 1];

    // lengths[b] (one block per batch writes it)
    if (blockIdx.x == 0 && tid == 0) {
        const size_t main_elems = (size_t)B_DIM * OUT_LEN * D_DIM;
        if ((size_t)out_size > main_elems)
            out[main_elems + b] = (float)total;
    }

    // ---- 64 binary searches: frame -> phoneme ----
    if (tid < FRAMES_PER_BLK) {
        const int j = base + tid;
        int ph = -1;
        if (j < total) {
            // lower_bound: first i with s_cum[i] > j; 11 iters for width 1024.
            int lo = 0, hi = TX;
            #pragma unroll
            for (int it = 0; it < 11; ++it) {
                int mid = (lo + hi) >> 1;
                if (s_cum[mid] > j) hi = mid; else lo = mid + 1;
            }
            ph = lo;
        }
        s_ph[tid] = ph;
    }
    __syncthreads();

    // ---- gather + store: 4 groups of 64 lanes, 16 frames each (2 x FPT=8) --
    const int group = tid >> 6;              // 0..3
    const int gl    = tid & 63;
    float4* out4 = (float4*)out;

    #pragma unroll
    for (int batch = 0; batch < 2; ++batch) {
        const int f0 = group * 16 + batch * FPT;   // frame offset in block

        int ph[FPT];
        #pragma unroll
        for (int k = 0; k < FPT; ++k) ph[k] = s_ph[f0 + k];

        float4 v[FPT];
        #pragma unroll
        for (int k = 0; k < FPT; ++k) {
            v[k] = make_float4(0.f, 0.f, 0.f, 0.f);
            if (ph[k] >= 0)
                v[k] = x4[((size_t)b * TX + ph[k]) * D_VEC + gl];
        }

        #pragma unroll
        for (int k = 0; k < FPT; ++k)
            out4[((size_t)b * OUT_LEN + base + f0 + k) * D_VEC + gl] = v[k];
    }
}

// ---------------------------------------------------------------------------
extern "C" void kernel_launch(void* const* d_in, const int* in_sizes, int n_in,
                              void* d_out, int out_size) {
    const float* x   = (const float*)d_in[0];   // (16,1024,256) fp32
    const int*   rep = (const int*)d_in[1];     // (16,1024) int32
    float* out = (float*)d_out;

    dim3 grid(OUT_LEN / FRAMES_PER_BLK, B_DIM); // (112, 16)
    fused_kernel<<<grid, 256>>>((const float4*)x, rep, out, out_size);
}